// round 1
// baseline (speedup 1.0000x reference)
#include <cuda_runtime.h>
#include <math_constants.h>

#define N_ROI 262144
#define DIM   256
#define HID   64
#define NNET  128

typedef unsigned long long ull;

// ---------------- scratch (no allocations allowed) ----------------
__device__ float g_score[N_ROI];
__device__ float g_wbuf[N_ROI];
__device__ int   g_list[N_ROI];
__device__ float g_segmax[NNET];
__device__ float g_denom[NNET];
__device__ int   g_count[NNET];
__device__ int   g_offset[NNET];
__device__ int   g_cursor[NNET];

// ---------------- init ----------------
__global__ void init_kernel() {
    int t = threadIdx.x;
    g_segmax[t] = -CUDART_INF_F;
    g_denom[t]  = 0.f;
    g_count[t]  = 0;
}

// ---------------- fused MLP score kernel ----------------
// score[i] = relu(x[i,:] @ W1 + b1) @ W2    (b2 cancels in softmax)
// Tile: 128 rows/block, 128 threads, thread tile = 8 rows x 8 cols (4 col-pairs).
// Uses packed fp32 FMA (fma.rn.f32x2): a = (x,x) dup pairs staged in smem,
// b = (w_j, w_j+1) pairs from a re-laid-out W1 slice.
__global__ __launch_bounds__(128, 4) void score_kernel(
    const float* __restrict__ x, const float* __restrict__ W1,
    const float* __restrict__ b1, const float* __restrict__ W2)
{
    __shared__ __align__(16) float2 sX[32 * 128];  // (x,x) dup, XOR-swizzled rows
    __shared__ __align__(16) float  sW[32 * 64];   // W1 chunk, pair-interleaved

    const int tid  = threadIdx.x;
    const int rg   = tid >> 3;   // 0..15 : row group (8 rows each)
    const int cg   = tid & 7;    // 0..7  : col group (8 cols each)
    const int row0 = blockIdx.x * 128;

    ull acc[8][4];
    #pragma unroll
    for (int rr = 0; rr < 8; rr++)
        #pragma unroll
        for (int cp = 0; cp < 4; cp++) acc[rr][cp] = 0ull;

    for (int kc = 0; kc < DIM; kc += 32) {
        __syncthreads();
        // stage x chunk: 128 rows x 32 k, duplicated into float2, swizzled
        #pragma unroll
        for (int i = 0; i < 8; i++) {
            int f   = i * 128 + tid;
            int row = f >> 3;
            int kq  = f & 7;
            float4 v = *(const float4*)(x + (size_t)(row0 + row) * DIM + kc + kq * 4);
            int rsw = row ^ (2 * kq);   // keeps STS.64 at the 2-wavefront floor
            sX[(kq * 4 + 0) * 128 + rsw] = make_float2(v.x, v.x);
            sX[(kq * 4 + 1) * 128 + rsw] = make_float2(v.y, v.y);
            sX[(kq * 4 + 2) * 128 + rsw] = make_float2(v.z, v.z);
            sX[(kq * 4 + 3) * 128 + rsw] = make_float2(v.w, v.w);
        }
        // stage W1 chunk: 32 x 64, interleave pairs so LDS.64 is conflict-free:
        // (k, j) -> sW[k*64 + ((j&7)>>1)*16 + ((j>>3)<<1) + (j&1)]
        #pragma unroll
        for (int i = 0; i < 16; i++) {
            int e = i * 128 + tid;
            int k = e >> 6, j = e & 63;
            sW[k * 64 + ((j & 7) >> 1) * 16 + ((j >> 3) << 1) + (j & 1)] =
                W1[(size_t)(kc + k) * 64 + j];
        }
        __syncthreads();

        #pragma unroll
        for (int k = 0; k < 32; k++) {
            const int sw = 2 * (k >> 2);
            ull a[8], b[4];
            #pragma unroll
            for (int rp = 0; rp < 4; rp++) {
                int q = (rg * 8 + rp * 2) ^ sw;            // even -> 16B aligned
                ulonglong2 av = *(const ulonglong2*)(sX + k * 128 + q);
                a[rp * 2]     = av.x;                      // (x_r,   x_r)
                a[rp * 2 + 1] = av.y;                      // (x_r+1, x_r+1)
            }
            #pragma unroll
            for (int cp = 0; cp < 4; cp++)
                b[cp] = *(const ull*)(sW + k * 64 + cp * 16 + cg * 2);
            #pragma unroll
            for (int cp = 0; cp < 4; cp++)
                #pragma unroll
                for (int rr = 0; rr < 8; rr++)
                    asm("fma.rn.f32x2 %0, %1, %2, %0;"
                        : "+l"(acc[rr][cp]) : "l"(a[rr]), "l"(b[cp]));
        }
    }

    // epilogue: +b1, relu, dot with W2, reduce over the 8 cg lanes
    float sc[8];
    #pragma unroll
    for (int rr = 0; rr < 8; rr++) sc[rr] = 0.f;
    #pragma unroll
    for (int cp = 0; cp < 4; cp++) {
        int j = cg * 8 + 2 * cp;
        float ba = b1[j], bb = b1[j + 1];
        float wa = W2[j], wb = W2[j + 1];
        #pragma unroll
        for (int rr = 0; rr < 8; rr++) {
            float2 hv = *(float2*)&acc[rr][cp];
            float h0 = fmaxf(hv.x + ba, 0.f);
            float h1 = fmaxf(hv.y + bb, 0.f);
            sc[rr] += h0 * wa + h1 * wb;
        }
    }
    #pragma unroll
    for (int o = 1; o < 8; o <<= 1)
        #pragma unroll
        for (int rr = 0; rr < 8; rr++)
            sc[rr] += __shfl_xor_sync(0xffffffffu, sc[rr], o);
    if (cg == 0) {
        #pragma unroll
        for (int rr = 0; rr < 8; rr++)
            g_score[row0 + rg * 8 + rr] = sc[rr];
    }
}

// ---------------- segment max + histogram ----------------
__global__ void maxcount_kernel(const int* __restrict__ group) {
    int i = blockIdx.x * blockDim.x + threadIdx.x;
    if (i >= N_ROI) return;
    int g = group[i];
    float v = g_score[i];
    if (v >= 0.f) atomicMax((int*)&g_segmax[g], __float_as_int(v));
    else          atomicMin((unsigned int*)&g_segmax[g], __float_as_uint(v));
    atomicAdd(&g_count[g], 1);
}

// ---------------- exclusive scan over 128 counts ----------------
__global__ void scan_kernel() {
    __shared__ int s[NNET];
    int t = threadIdx.x;
    s[t] = g_count[t];
    __syncthreads();
    int sum = 0;
    for (int i = 0; i < t; i++) sum += s[i];
    g_offset[t] = sum;
    g_cursor[t] = sum;
}

// ---------------- exp, denom, scatter into per-group bins ----------------
__global__ void expscatter_kernel(const int* __restrict__ group) {
    int i = blockIdx.x * blockDim.x + threadIdx.x;
    if (i >= N_ROI) return;
    int g = group[i];
    float w = expf(g_score[i] - g_segmax[g]);
    atomicAdd(&g_denom[g], w);
    int pos = atomicAdd(&g_cursor[g], 1);
    g_list[pos] = i;
    g_wbuf[pos] = w;
}

// ---------------- weighted pooling: out[g,:] = sum(w*x)/sum(w) ----------------
// grid = NNET*4 blocks: (group, 64-col chunk). block = 256 threads =
// 16 row-slots x 16 float4-col threads. Pure streaming reads, no atomics.
__global__ __launch_bounds__(256) void pool_kernel(
    const float* __restrict__ x, float* __restrict__ out)
{
    int g     = blockIdx.x >> 2;
    int chunk = blockIdx.x & 3;
    int rs    = threadIdx.x >> 4;
    int ct    = threadIdx.x & 15;
    int start = g_offset[g];
    int cnt   = g_count[g];
    int cbase = chunk * 16 + ct;
    const float4* __restrict__ x4 = (const float4*)x;

    float4 acc = make_float4(0.f, 0.f, 0.f, 0.f);
    int r = rs;
    for (; r + 48 < cnt; r += 64) {
        int base = start + r;
        int i0 = g_list[base];      int i1 = g_list[base + 16];
        int i2 = g_list[base + 32]; int i3 = g_list[base + 48];
        float w0 = g_wbuf[base];      float w1 = g_wbuf[base + 16];
        float w2 = g_wbuf[base + 32]; float w3 = g_wbuf[base + 48];
        float4 v0 = x4[(size_t)i0 * 64 + cbase];
        float4 v1 = x4[(size_t)i1 * 64 + cbase];
        float4 v2 = x4[(size_t)i2 * 64 + cbase];
        float4 v3 = x4[(size_t)i3 * 64 + cbase];
        acc.x += w0 * v0.x; acc.y += w0 * v0.y; acc.z += w0 * v0.z; acc.w += w0 * v0.w;
        acc.x += w1 * v1.x; acc.y += w1 * v1.y; acc.z += w1 * v1.z; acc.w += w1 * v1.w;
        acc.x += w2 * v2.x; acc.y += w2 * v2.y; acc.z += w2 * v2.z; acc.w += w2 * v2.w;
        acc.x += w3 * v3.x; acc.y += w3 * v3.y; acc.z += w3 * v3.z; acc.w += w3 * v3.w;
    }
    for (; r < cnt; r += 16) {
        int idx = g_list[start + r];
        float w = g_wbuf[start + r];
        float4 v = x4[(size_t)idx * 64 + cbase];
        acc.x += w * v.x; acc.y += w * v.y; acc.z += w * v.z; acc.w += w * v.w;
    }

    __shared__ float4 red[16][16];
    red[rs][ct] = acc;
    __syncthreads();
    if (rs == 0) {
        float4 s = red[0][ct];
        #pragma unroll
        for (int k = 1; k < 16; k++) {
            float4 t = red[k][ct];
            s.x += t.x; s.y += t.y; s.z += t.z; s.w += t.w;
        }
        float den = g_denom[g];
        float inv = (den > 0.f) ? (1.f / den) : 0.f;
        s.x *= inv; s.y *= inv; s.z *= inv; s.w *= inv;
        ((float4*)out)[(size_t)g * 64 + cbase] = s;
    }
}

// ---------------- launch ----------------
extern "C" void kernel_launch(void* const* d_in, const int* in_sizes, int n_in,
                              void* d_out, int out_size) {
    const float* x   = (const float*)d_in[0];
    const int*   grp = (const int*)d_in[1];
    const float* W1  = (const float*)d_in[2];
    const float* b1  = (const float*)d_in[3];
    const float* W2  = (const float*)d_in[4];
    // b2 (d_in[5]) cancels under softmax shift-invariance.

    init_kernel<<<1, NNET>>>();
    score_kernel<<<N_ROI / 128, 128>>>(x, W1, b1, W2);
    maxcount_kernel<<<N_ROI / 256, 256>>>(grp);
    scan_kernel<<<1, NNET>>>();
    expscatter_kernel<<<N_ROI / 256, 256>>>(grp);
    pool_kernel<<<NNET * 4, 256>>>(x, (float*)d_out);
}

// round 2
// speedup vs baseline: 1.2022x; 1.2022x over previous
#include <cuda_runtime.h>

#define N_ROI 262144
#define DIM   256
#define HID   64
#define NNET  128

#define KC     16              // k per chunk
#define NCH    (DIM / KC)      // 16 chunks
#define ROWS_B 256             // rows per block
#define SLOTS  136             // 128 row-pairs, skewed p + (p>>4) -> max 134

typedef unsigned long long ull;

// ---------------- scratch (no allocations allowed) ----------------
__device__ float g_score[N_ROI];
__device__ ull   g_pair[N_ROI];      // (w_bits << 32) | row_index
__device__ int   g_maxbits[NNET];    // segment max, monotone int encoding
__device__ float g_denom[NNET];
__device__ int   g_count[NNET];
__device__ int   g_offset[NNET];
__device__ int   g_cursor[NNET];
__device__ int   g_done;

// ---------------- init ----------------
__global__ void init_kernel() {
    int t = threadIdx.x;
    g_maxbits[t] = 0xFF800000;       // -inf bits
    g_denom[t]   = 0.f;
    g_count[t]   = 0;
    if (t == 0) g_done = 0;
}

// ---------------- fused: MLP score + segment max + histogram + scan ----------------
// score[i] = relu(x[i,:] @ W1 + b1) @ W2   (b2 cancels under softmax shift)
// Block: 128 threads, tile 256 rows x 64 cols. Thread tile: 16 rows (8 f32x2
// row-pairs) x 8 cols. a = genuine (x_r, x_r+1) pairs (no dup), b = (w,w) dup.
// 128B LDS per 64 FFMA2 = balanced with the FFMA2 pipe.
__global__ __launch_bounds__(128, 2) void score_kernel(
    const float* __restrict__ x,  const float* __restrict__ W1,
    const float* __restrict__ b1, const float* __restrict__ W2,
    const int* __restrict__ group)
{
    __shared__ __align__(16) float2 sX[KC][SLOTS];   // (x[2p][k], x[2p+1][k])
    __shared__ __align__(16) float2 sW[KC][HID];     // (w, w) dup
    __shared__ int sMax[NNET];
    __shared__ int sCnt[NNET];
    __shared__ int sScan[NNET];
    __shared__ int sFlag;

    const int tid  = threadIdx.x;
    const int rg   = tid >> 3;          // 0..15, 16 rows each
    const int cg   = tid & 7;           // cols {cg + 8c}
    const int row0 = blockIdx.x * ROWS_B;
    const int sbase = 8 * rg + (rg >> 1);   // skewed pair-slot base (conflict-free)

    if (tid < NNET) { sMax[tid] = 0xFF800000; sCnt[tid] = 0; }

    ull acc[8][8];
    #pragma unroll
    for (int pp = 0; pp < 8; pp++)
        #pragma unroll
        for (int cc = 0; cc < 8; cc++) acc[pp][cc] = 0ull;

    // register prefetch of chunk 0
    const float4* __restrict__ x4 = (const float4*)x;
    float4 vx[8];
    float  ww[8];
    #pragma unroll
    for (int i = 0; i < 8; i++) {
        int idx = i * 128 + tid, row = idx >> 2, kq = idx & 3;
        vx[i] = x4[(size_t)(row0 + row) * 64 + kq];
        int e = i * 128 + tid, k = e >> 6, j = e & 63;
        ww[i] = W1[(size_t)k * HID + j];
    }

    for (int c = 0; c < NCH; c++) {
        __syncthreads();                 // prior compute done reading smem
        // stage x chunk (transpose into row-pairs, skewed slots)
        #pragma unroll
        for (int i = 0; i < 8; i++) {
            int idx = i * 128 + tid, row = idx >> 2, kq = idx & 3;
            int p = row >> 1, half = row & 1, slot = p + (p >> 4);
            float4 v = vx[i];
            ((float*)&sX[kq * 4 + 0][slot])[half] = v.x;
            ((float*)&sX[kq * 4 + 1][slot])[half] = v.y;
            ((float*)&sX[kq * 4 + 2][slot])[half] = v.z;
            ((float*)&sX[kq * 4 + 3][slot])[half] = v.w;
        }
        // stage W chunk (duplicated pairs)
        #pragma unroll
        for (int i = 0; i < 8; i++) {
            int e = i * 128 + tid, k = e >> 6, j = e & 63;
            sW[k][j] = make_float2(ww[i], ww[i]);
        }
        // prefetch next chunk while this one computes
        if (c + 1 < NCH) {
            #pragma unroll
            for (int i = 0; i < 8; i++) {
                int idx = i * 128 + tid, row = idx >> 2, kq = idx & 3;
                vx[i] = x4[(size_t)(row0 + row) * 64 + (c + 1) * 4 + kq];
                int e = i * 128 + tid, k = e >> 6, j = e & 63;
                ww[i] = W1[(size_t)((c + 1) * KC + k) * HID + j];
            }
        }
        __syncthreads();

        #pragma unroll 4
        for (int k = 0; k < KC; k++) {
            float2 a[8];
            ull    b[8];
            #pragma unroll
            for (int pp = 0; pp < 8; pp++) a[pp] = sX[k][sbase + pp];
            #pragma unroll
            for (int cc = 0; cc < 8; cc++) b[cc] = *(const ull*)&sW[k][cg + 8 * cc];
            #pragma unroll
            for (int cc = 0; cc < 8; cc++)
                #pragma unroll
                for (int pp = 0; pp < 8; pp++)
                    asm("fma.rn.f32x2 %0, %1, %2, %0;"
                        : "+l"(acc[pp][cc]) : "l"(*(ull*)&a[pp]), "l"(b[cc]));
        }
    }

    // epilogue: +b1, relu, dot W2 (per thread's 8 cols), reduce across cg lanes
    float2 s[8];
    #pragma unroll
    for (int pp = 0; pp < 8; pp++) s[pp] = make_float2(0.f, 0.f);
    #pragma unroll
    for (int cc = 0; cc < 8; cc++) {
        int col = cg + 8 * cc;
        float bb = b1[col], w2 = W2[col];
        #pragma unroll
        for (int pp = 0; pp < 8; pp++) {
            float2 h = *(float2*)&acc[pp][cc];
            s[pp].x += fmaxf(h.x + bb, 0.f) * w2;
            s[pp].y += fmaxf(h.y + bb, 0.f) * w2;
        }
    }
    #pragma unroll
    for (int o = 1; o < 8; o <<= 1)
        #pragma unroll
        for (int pp = 0; pp < 8; pp++) {
            s[pp].x += __shfl_xor_sync(0xffffffffu, s[pp].x, o);
            s[pp].y += __shfl_xor_sync(0xffffffffu, s[pp].y, o);
        }

    if (cg == 0) {
        #pragma unroll
        for (int pp = 0; pp < 8; pp++) {
            int r = row0 + rg * 16 + 2 * pp;
            *(float2*)&g_score[r] = s[pp];
            int2 gg = *(const int2*)&group[r];
            // smem segment max (monotone two-sided trick) + count
            atomicAdd(&sCnt[gg.x], 1);
            atomicAdd(&sCnt[gg.y], 1);
            int bx = __float_as_int(s[pp].x);
            int by = __float_as_int(s[pp].y);
            if (s[pp].x >= 0.f) atomicMax(&sMax[gg.x], bx);
            else                atomicMin((unsigned*)&sMax[gg.x], (unsigned)bx);
            if (s[pp].y >= 0.f) atomicMax(&sMax[gg.y], by);
            else                atomicMin((unsigned*)&sMax[gg.y], (unsigned)by);
        }
    }
    __syncthreads();

    // flush block histogram to globals
    if (tid < NNET && sCnt[tid] > 0) {
        atomicAdd(&g_count[tid], sCnt[tid]);
        int b = sMax[tid];
        if (__int_as_float(b) >= 0.f) atomicMax(&g_maxbits[tid], b);
        else                          atomicMin((unsigned*)&g_maxbits[tid], (unsigned)b);
    }
    __threadfence();
    __syncthreads();

    // last block performs the 128-entry exclusive scan (kills a launch)
    if (tid == 0) {
        int t = atomicAdd(&g_done, 1);
        sFlag = (t == (int)gridDim.x - 1);
    }
    __syncthreads();
    if (sFlag) {
        int own = g_count[tid];
        sScan[tid] = own;
        __syncthreads();
        #pragma unroll
        for (int o = 1; o < NNET; o <<= 1) {
            int add = (tid >= o) ? sScan[tid - o] : 0;
            __syncthreads();
            sScan[tid] += add;
            __syncthreads();
        }
        int off = sScan[tid] - own;
        g_offset[tid] = off;
        g_cursor[tid] = off;
        if (tid == 0) g_done = 0;
    }
}

// ---------------- exp, denom, scatter (packed 8B records) ----------------
__global__ void expscatter_kernel(const int* __restrict__ group) {
    int i = blockIdx.x * blockDim.x + threadIdx.x;
    int g = group[i];
    float m = __int_as_float(g_maxbits[g]);
    float w = expf(g_score[i] - m);
    atomicAdd(&g_denom[g], w);
    int pos = atomicAdd(&g_cursor[g], 1);
    g_pair[pos] = ((ull)(unsigned)__float_as_int(w) << 32) | (unsigned)i;
}

// ---------------- weighted pooling ----------------
// grid = NNET*8 blocks: (group, 32-col chunk). block = 256 = 32 row-slots x 8
// float4-col threads. Streaming gather, no atomics.
__global__ __launch_bounds__(256) void pool_kernel(
    const float* __restrict__ x, float* __restrict__ out)
{
    int g     = blockIdx.x >> 3;
    int chunk = blockIdx.x & 7;
    int rs    = threadIdx.x >> 3;
    int ct    = threadIdx.x & 7;
    int start = g_offset[g];
    int cnt   = g_count[g];
    int cb    = chunk * 8 + ct;
    const float4* __restrict__ x4 = (const float4*)x;

    float4 acc = make_float4(0.f, 0.f, 0.f, 0.f);
    int r = rs;
    for (; r + 96 < cnt; r += 128) {
        ull p0 = g_pair[start + r];
        ull p1 = g_pair[start + r + 32];
        ull p2 = g_pair[start + r + 64];
        ull p3 = g_pair[start + r + 96];
        float w0 = __int_as_float((int)(p0 >> 32));
        float w1 = __int_as_float((int)(p1 >> 32));
        float w2 = __int_as_float((int)(p2 >> 32));
        float w3 = __int_as_float((int)(p3 >> 32));
        float4 v0 = x4[(size_t)(unsigned)p0 * 64 + cb];
        float4 v1 = x4[(size_t)(unsigned)p1 * 64 + cb];
        float4 v2 = x4[(size_t)(unsigned)p2 * 64 + cb];
        float4 v3 = x4[(size_t)(unsigned)p3 * 64 + cb];
        acc.x += w0 * v0.x; acc.y += w0 * v0.y; acc.z += w0 * v0.z; acc.w += w0 * v0.w;
        acc.x += w1 * v1.x; acc.y += w1 * v1.y; acc.z += w1 * v1.z; acc.w += w1 * v1.w;
        acc.x += w2 * v2.x; acc.y += w2 * v2.y; acc.z += w2 * v2.z; acc.w += w2 * v2.w;
        acc.x += w3 * v3.x; acc.y += w3 * v3.y; acc.z += w3 * v3.z; acc.w += w3 * v3.w;
    }
    for (; r < cnt; r += 32) {
        ull p = g_pair[start + r];
        float w = __int_as_float((int)(p >> 32));
        float4 v = x4[(size_t)(unsigned)p * 64 + cb];
        acc.x += w * v.x; acc.y += w * v.y; acc.z += w * v.z; acc.w += w * v.w;
    }

    __shared__ float4 red[32][8];
    red[rs][ct] = acc;
    __syncthreads();
    #pragma unroll
    for (int o = 16; o >= 1; o >>= 1) {
        if (rs < o) {
            float4 t = red[rs + o][ct];
            float4 u = red[rs][ct];
            u.x += t.x; u.y += t.y; u.z += t.z; u.w += t.w;
            red[rs][ct] = u;
        }
        __syncthreads();
    }
    if (rs == 0) {
        float den = g_denom[g];
        float inv = (den > 0.f) ? (1.f / den) : 0.f;
        float4 v = red[0][ct];
        v.x *= inv; v.y *= inv; v.z *= inv; v.w *= inv;
        ((float4*)out)[(size_t)g * 64 + cb] = v;
    }
}

// ---------------- launch ----------------
extern "C" void kernel_launch(void* const* d_in, const int* in_sizes, int n_in,
                              void* d_out, int out_size) {
    const float* x   = (const float*)d_in[0];
    const int*   grp = (const int*)d_in[1];
    const float* W1  = (const float*)d_in[2];
    const float* b1  = (const float*)d_in[3];
    const float* W2  = (const float*)d_in[4];
    // b2 (d_in[5]) cancels under softmax shift-invariance.

    init_kernel<<<1, NNET>>>();
    score_kernel<<<N_ROI / ROWS_B, 128>>>(x, W1, b1, W2, grp);
    expscatter_kernel<<<N_ROI / 256, 256>>>(grp);
    pool_kernel<<<NNET * 8, 256>>>(x, (float*)d_out);
}

// round 4
// speedup vs baseline: 2.2616x; 1.8813x over previous
#include <cuda_runtime.h>
#include <cuda_bf16.h>
#include <cstdint>

#define N_ROI 262144
#define DIM   256
#define HID   64
#define NNET  128
#define TILE_M 128
#define NTILE (N_ROI / TILE_M)   // 2048

typedef unsigned long long ull;

// ---------------- scratch ----------------
__device__ float g_score[N_ROI];
__device__ ull   g_pair[N_ROI];
__device__ __align__(16) __nv_bfloat16 g_WtH[HID * DIM];  // W1^T hi [64][256]
__device__ __align__(16) __nv_bfloat16 g_WtL[HID * DIM];  // W1^T lo
__device__ int   g_maxbits[NNET];
__device__ float g_denom[NNET];
__device__ int   g_count[NNET];
__device__ int   g_offset[NNET];
__device__ int   g_cursor[NNET];
__device__ int   g_done;

// ---------------- smem layout (byte offsets from 1024-aligned base) --------
#define OFF_B1   0
#define OFF_W2   256
#define OFF_MAX  512
#define OFF_CNT  1024
#define OFF_SCAN 1536
#define OFF_FLAG 2048
#define OFF_BH   4096            // 4 chunks x 8KB  = 32KB
#define OFF_BL   36864           // 32KB
#define OFF_AH   69632           // 16KB (single buffer)
#define OFF_AL   86016           // 16KB
#define SMEM_END 102400
#define DSMEM_BYTES (SMEM_END + 1024)

__device__ __forceinline__ uint32_t smem_u32(const void* p) {
    uint32_t a;
    asm("{ .reg .u64 t; cvta.to.shared.u64 t, %1; cvt.u32.u64 %0, t; }"
        : "=r"(a) : "l"(p));
    return a;
}

#define LDSM4(R, ADDR) asm volatile( \
    "ldmatrix.sync.aligned.m8n8.x4.shared.b16 {%0,%1,%2,%3}, [%4];" \
    : "=r"((R)[0]), "=r"((R)[1]), "=r"((R)[2]), "=r"((R)[3]) : "r"(ADDR))

#define MMA(D, A, B0, B1) asm volatile( \
    "mma.sync.aligned.m16n8k16.row.col.f32.bf16.bf16.f32 " \
    "{%0,%1,%2,%3}, {%4,%5,%6,%7}, {%8,%9}, {%0,%1,%2,%3};" \
    : "+f"((D)[0]), "+f"((D)[1]), "+f"((D)[2]), "+f"((D)[3]) \
    : "r"((A)[0]), "r"((A)[1]), "r"((A)[2]), "r"((A)[3]), "r"(B0), "r"(B1))

__device__ __forceinline__ void cvt8(const float4& a, const float4& b,
                                     uint4& hi, uint4& lo) {
    float f[8] = {a.x, a.y, a.z, a.w, b.x, b.y, b.z, b.w};
    unsigned h[8], l[8];
    #pragma unroll
    for (int i = 0; i < 8; i++) {
        __nv_bfloat16 hb = __float2bfloat16_rn(f[i]);
        __nv_bfloat16 lb = __float2bfloat16_rn(f[i] - __bfloat162float(hb));
        h[i] = (unsigned)__bfloat16_as_ushort(hb);
        l[i] = (unsigned)__bfloat16_as_ushort(lb);
    }
    hi = make_uint4(h[0] | (h[1] << 16), h[2] | (h[3] << 16),
                    h[4] | (h[5] << 16), h[6] | (h[7] << 16));
    lo = make_uint4(l[0] | (l[1] << 16), l[2] | (l[3] << 16),
                    l[4] | (l[5] << 16), l[6] | (l[7] << 16));
}

// ---------------- prep: W1^T hi/lo split + global init ----------------
__global__ void prep_kernel(const float* __restrict__ W1) {
    int t = blockIdx.x * 256 + threadIdx.x;          // 16384 threads
    int j = t >> 8, k = t & 255;
    float v = W1[(size_t)k * HID + j];
    __nv_bfloat16 h = __float2bfloat16_rn(v);
    __nv_bfloat16 l = __float2bfloat16_rn(v - __bfloat162float(h));
    g_WtH[j * DIM + k] = h;
    g_WtL[j * DIM + k] = l;
    if (t < NNET) { g_maxbits[t] = 0xFF800000; g_denom[t] = 0.f; g_count[t] = 0; }
    if (t == 0) g_done = 0;
}

// ---------------- score: bf16-split HMMA GEMM + epilogue + hist + scan -----
__global__ __launch_bounds__(256, 2) void score_kernel(
    const float* __restrict__ x, const float* __restrict__ b1,
    const float* __restrict__ W2, const int* __restrict__ group)
{
    extern __shared__ char dsm[];
    uint32_t raw = smem_u32(dsm);
    uint32_t sb  = (raw + 1023) & ~1023u;
    char* s = dsm + (sb - raw);

    float* sB1  = (float*)(s + OFF_B1);
    float* sW2  = (float*)(s + OFF_W2);
    int*   sMax = (int*)(s + OFF_MAX);
    int*   sCnt = (int*)(s + OFF_CNT);
    int*   sScan= (int*)(s + OFF_SCAN);
    int*   sFlag= (int*)(s + OFF_FLAG);

    const int tid = threadIdx.x;
    const int w   = tid >> 5, l = tid & 31;
    const int row0 = blockIdx.x * TILE_M;
    const float4* __restrict__ x4 = (const float4*)x;

    if (tid < 64) { sB1[tid] = b1[tid]; sW2[tid] = W2[tid]; }
    if (tid < NNET) { sMax[tid] = 0xFF800000; sCnt[tid] = 0; }

    // ---- stage W1^T hi/lo into smem (all 4 K-chunks, swizzled) ----
    #pragma unroll
    for (int it = 0; it < 8; it++) {
        int f = it * 256 + tid;          // 2048 16B-groups
        int c = f >> 9, rem = f & 511, n = rem >> 3, kg = rem & 7;
        int src = n * DIM + c * 64 + kg * 8;
        uint32_t dst = c * 8192 + n * 128 + ((kg * 16) ^ ((n & 7) * 16));
        *(uint4*)(s + OFF_BH + dst) = *(const uint4*)(g_WtH + src);
        *(uint4*)(s + OFF_BL + dst) = *(const uint4*)(g_WtL + src);
    }

    // ---- ldmatrix address precompute ----
    const uint32_t xw  = (l & 7) * 16;                   // swizzle xor
    const uint32_t a_row = w * 16 + ((l >> 3) & 1) * 8 + (l & 7);
    const uint32_t a_off = a_row * 128;
    const uint32_t a_x   = (a_row & 7) * 16;
    const uint32_t a_cb  = (l >> 4) * 16;
    const uint32_t b_rb  = ((l >> 4) * 8 + (l & 7)) * 128;  // + q*2048
    const uint32_t b_cb  = ((l >> 3) & 1) * 16;

    float d[8][4];
    #pragma unroll
    for (int i = 0; i < 8; i++)
        #pragma unroll
        for (int j = 0; j < 4; j++) d[i][j] = 0.f;

    float4 rA[4][2];
    #define LDG_A(c) do { \
        _Pragma("unroll") for (int it = 0; it < 4; it++) { \
            int f = it * 256 + tid, row = f >> 3, kg = f & 7; \
            const float4* p = x4 + ((size_t)(row0 + row) * 64 + (c) * 16 + kg * 2); \
            rA[it][0] = p[0]; rA[it][1] = p[1]; } \
    } while (0)

    LDG_A(0);

    #pragma unroll
    for (int c = 0; c < 4; c++) {
        __syncthreads();                       // prior compute done with A smem
        #pragma unroll
        for (int it = 0; it < 4; it++) {
            int f = it * 256 + tid, row = f >> 3, kg = f & 7;
            uint32_t off = row * 128 + ((kg * 16) ^ ((row & 7) * 16));
            uint4 hi, lo; cvt8(rA[it][0], rA[it][1], hi, lo);
            *(uint4*)(s + OFF_AH + off) = hi;
            *(uint4*)(s + OFF_AL + off) = lo;
        }
        __syncthreads();
        if (c < 3) LDG_A(c + 1);               // prefetch overlaps compute

        const uint32_t BHc = sb + OFF_BH + c * 8192;
        const uint32_t BLc = sb + OFF_BL + c * 8192;
        const uint32_t AHb = sb + OFF_AH, ALb = sb + OFF_AL;

        #pragma unroll
        for (int t = 0; t < 4; t++) {
            const uint32_t tcol = t * 32;
            uint32_t ah[4], al[4];
            uint32_t aaddr = a_off + ((tcol + a_cb) ^ a_x);
            LDSM4(ah, AHb + aaddr);
            LDSM4(al, ALb + aaddr);
            #pragma unroll
            for (int q = 0; q < 4; q++) {
                uint32_t bh[4], bl[4];
                uint32_t baddr = q * 2048 + b_rb + ((tcol + b_cb) ^ xw);
                LDSM4(bh, BHc + baddr);
                LDSM4(bl, BLc + baddr);
                MMA(d[2 * q],     ah, bh[0], bh[1]);
                MMA(d[2 * q],     al, bh[0], bh[1]);
                MMA(d[2 * q],     ah, bl[0], bl[1]);
                MMA(d[2 * q + 1], ah, bh[2], bh[3]);
                MMA(d[2 * q + 1], al, bh[2], bh[3]);
                MMA(d[2 * q + 1], ah, bl[2], bl[3]);
            }
        }
    }

    // ---- epilogue: relu(D + b1) . W2, quad reduce, write + hist ----
    float sA = 0.f, sB = 0.f;
    #pragma unroll
    for (int nt = 0; nt < 8; nt++) {
        int j0 = nt * 8 + (l & 3) * 2;
        float b0 = sB1[j0], b1v = sB1[j0 + 1];
        float w0 = sW2[j0], w1v = sW2[j0 + 1];
        sA += fmaxf(d[nt][0] + b0, 0.f) * w0 + fmaxf(d[nt][1] + b1v, 0.f) * w1v;
        sB += fmaxf(d[nt][2] + b0, 0.f) * w0 + fmaxf(d[nt][3] + b1v, 0.f) * w1v;
    }
    sA += __shfl_xor_sync(0xffffffffu, sA, 1);
    sA += __shfl_xor_sync(0xffffffffu, sA, 2);
    sB += __shfl_xor_sync(0xffffffffu, sB, 1);
    sB += __shfl_xor_sync(0xffffffffu, sB, 2);

    if ((l & 3) == 0) {
        int r1 = w * 16 + (l >> 2);
        int r2 = r1 + 8;
        g_score[row0 + r1] = sA;
        g_score[row0 + r2] = sB;
        int g1 = group[row0 + r1], g2 = group[row0 + r2];
        atomicAdd(&sCnt[g1], 1);
        atomicAdd(&sCnt[g2], 1);
        int bA = __float_as_int(sA), bB = __float_as_int(sB);
        if (sA >= 0.f) atomicMax(&sMax[g1], bA);
        else           atomicMin((unsigned*)&sMax[g1], (unsigned)bA);
        if (sB >= 0.f) atomicMax(&sMax[g2], bB);
        else           atomicMin((unsigned*)&sMax[g2], (unsigned)bB);
    }
    __syncthreads();

    // flush block hist to globals
    if (tid < NNET && sCnt[tid] > 0) {
        atomicAdd(&g_count[tid], sCnt[tid]);
        int b = sMax[tid];
        if (__int_as_float(b) >= 0.f) atomicMax(&g_maxbits[tid], b);
        else                          atomicMin((unsigned*)&g_maxbits[tid], (unsigned)b);
    }
    __threadfence();
    __syncthreads();

    // last block: 128-entry exclusive scan
    if (tid == 0) {
        int t = atomicAdd(&g_done, 1);
        *sFlag = (t == (int)gridDim.x - 1);
    }
    __syncthreads();
    if (*sFlag) {
        if (tid < NNET) sScan[tid] = g_count[tid];
        __syncthreads();
        if (tid < NNET) {
            int acc = 0;
            for (int i = 0; i < tid; i++) acc += sScan[i];
            g_offset[tid] = acc;
            g_cursor[tid] = acc;
        }
        if (tid == 0) g_done = 0;
    }
}

// ---------------- exp + denom + scatter (block-aggregated atomics) ---------
__global__ __launch_bounds__(1024) void expscatter_kernel(const int* __restrict__ group) {
    __shared__ int   sCnt[NNET];
    __shared__ int   sCur[NNET];
    __shared__ float sDen[NNET];
    int tid = threadIdx.x;
    int i = blockIdx.x * 1024 + tid;
    if (tid < NNET) { sCnt[tid] = 0; sDen[tid] = 0.f; }
    __syncthreads();
    int g = group[i];
    float m = __int_as_float(g_maxbits[g]);
    float w = __expf(g_score[i] - m);
    atomicAdd(&sDen[g], w);
    atomicAdd(&sCnt[g], 1);
    __syncthreads();
    if (tid < NNET && sCnt[tid] > 0) {
        atomicAdd(&g_denom[tid], sDen[tid]);
        sCur[tid] = atomicAdd(&g_cursor[tid], sCnt[tid]);
    }
    __syncthreads();
    int pos = atomicAdd(&sCur[g], 1);
    g_pair[pos] = ((ull)(unsigned)__float_as_int(w) << 32) | (unsigned)i;
}

// ---------------- weighted pooling (73% DRAM, unchanged) -------------------
__global__ __launch_bounds__(256) void pool_kernel(
    const float* __restrict__ x, float* __restrict__ out)
{
    int g     = blockIdx.x >> 3;
    int chunk = blockIdx.x & 7;
    int rs    = threadIdx.x >> 3;
    int ct    = threadIdx.x & 7;
    int start = g_offset[g];
    int cnt   = g_count[g];
    int cb    = chunk * 8 + ct;
    const float4* __restrict__ x4 = (const float4*)x;

    float4 acc = make_float4(0.f, 0.f, 0.f, 0.f);
    int r = rs;
    for (; r + 96 < cnt; r += 128) {
        ull p0 = g_pair[start + r];
        ull p1 = g_pair[start + r + 32];
        ull p2 = g_pair[start + r + 64];
        ull p3 = g_pair[start + r + 96];
        float w0 = __int_as_float((int)(p0 >> 32));
        float w1 = __int_as_float((int)(p1 >> 32));
        float w2 = __int_as_float((int)(p2 >> 32));
        float w3 = __int_as_float((int)(p3 >> 32));
        float4 v0 = x4[(size_t)(unsigned)p0 * 64 + cb];
        float4 v1 = x4[(size_t)(unsigned)p1 * 64 + cb];
        float4 v2 = x4[(size_t)(unsigned)p2 * 64 + cb];
        float4 v3 = x4[(size_t)(unsigned)p3 * 64 + cb];
        acc.x += w0 * v0.x; acc.y += w0 * v0.y; acc.z += w0 * v0.z; acc.w += w0 * v0.w;
        acc.x += w1 * v1.x; acc.y += w1 * v1.y; acc.z += w1 * v1.z; acc.w += w1 * v1.w;
        acc.x += w2 * v2.x; acc.y += w2 * v2.y; acc.z += w2 * v2.z; acc.w += w2 * v2.w;
        acc.x += w3 * v3.x; acc.y += w3 * v3.y; acc.z += w3 * v3.z; acc.w += w3 * v3.w;
    }
    for (; r < cnt; r += 32) {
        ull p = g_pair[start + r];
        float w = __int_as_float((int)(p >> 32));
        float4 v = x4[(size_t)(unsigned)p * 64 + cb];
        acc.x += w * v.x; acc.y += w * v.y; acc.z += w * v.z; acc.w += w * v.w;
    }

    __shared__ float4 red[32][8];
    red[rs][ct] = acc;
    __syncthreads();
    #pragma unroll
    for (int o = 16; o >= 1; o >>= 1) {
        if (rs < o) {
            float4 t = red[rs + o][ct];
            float4 u = red[rs][ct];
            u.x += t.x; u.y += t.y; u.z += t.z; u.w += t.w;
            red[rs][ct] = u;
        }
        __syncthreads();
    }
    if (rs == 0) {
        float den = g_denom[g];
        float inv = (den > 0.f) ? (1.f / den) : 0.f;
        float4 v = red[0][ct];
        v.x *= inv; v.y *= inv; v.z *= inv; v.w *= inv;
        ((float4*)out)[(size_t)g * 64 + cb] = v;
    }
}

// ---------------- launch ----------------
extern "C" void kernel_launch(void* const* d_in, const int* in_sizes, int n_in,
                              void* d_out, int out_size) {
    const float* x   = (const float*)d_in[0];
    const int*   grp = (const int*)d_in[1];
    const float* W1  = (const float*)d_in[2];
    const float* b1  = (const float*)d_in[3];
    const float* W2  = (const float*)d_in[4];
    // b2 (d_in[5]) cancels under softmax shift-invariance.

    cudaFuncSetAttribute(score_kernel,
        cudaFuncAttributeMaxDynamicSharedMemorySize, DSMEM_BYTES);

    prep_kernel<<<64, 256>>>(W1);
    score_kernel<<<NTILE, 256, DSMEM_BYTES>>>(x, b1, W2, grp);
    expscatter_kernel<<<N_ROI / 1024, 1024>>>(grp);
    pool_kernel<<<NNET * 8, 256>>>(x, (float*)d_out);
}

// round 5
// speedup vs baseline: 2.4432x; 1.0803x over previous
#include <cuda_runtime.h>
#include <cuda_bf16.h>
#include <cstdint>

#define N_ROI 262144
#define DIM   256
#define HID   64
#define NNET  128
#define TILE_M 128
#define NTILE (N_ROI / TILE_M)   // 2048

typedef unsigned long long ull;

// ---------------- scratch ----------------
__device__ float g_w[N_ROI];                              // exp(score)
__device__ ull   g_pair[N_ROI];
__device__ __align__(16) __nv_bfloat16 g_WtH[HID * DIM];  // W1^T hi [64][256]
__device__ __align__(16) __nv_bfloat16 g_WtL[HID * DIM];  // W1^T lo
__device__ int   g_count[NNET];
__device__ int   g_offset[NNET];
__device__ int   g_cursor[NNET];
__device__ int   g_done;

// ---------------- smem layout (byte offsets from 1024-aligned base) --------
#define OFF_B1   0
#define OFF_W2   256
#define OFF_CNT  512
#define OFF_SCAN 1024
#define OFF_FLAG 1536
#define OFF_A    2048            // 2 bufs x (16KB hi + 16KB lo) = 64KB
#define OFF_B    67584           // 2 bufs x (8KB hi + 8KB lo)   = 32KB
#define SMEM_END 100352
#define DSMEM_BYTES (SMEM_END + 1024)

__device__ __forceinline__ uint32_t smem_u32(const void* p) {
    uint32_t a;
    asm("{ .reg .u64 t; cvta.to.shared.u64 t, %1; cvt.u32.u64 %0, t; }"
        : "=r"(a) : "l"(p));
    return a;
}

#define LDSM4(R, ADDR) asm volatile( \
    "ldmatrix.sync.aligned.m8n8.x4.shared.b16 {%0,%1,%2,%3}, [%4];" \
    : "=r"((R)[0]), "=r"((R)[1]), "=r"((R)[2]), "=r"((R)[3]) : "r"(ADDR))

#define MMA(D, A, B0, B1) asm volatile( \
    "mma.sync.aligned.m16n8k16.row.col.f32.bf16.bf16.f32 " \
    "{%0,%1,%2,%3}, {%4,%5,%6,%7}, {%8,%9}, {%0,%1,%2,%3};" \
    : "+f"((D)[0]), "+f"((D)[1]), "+f"((D)[2]), "+f"((D)[3]) \
    : "r"((A)[0]), "r"((A)[1]), "r"((A)[2]), "r"((A)[3]), "r"(B0), "r"(B1))

// packed fp32 -> bf16 hi/lo split: 2 values per cvt.rn.bf16x2
__device__ __forceinline__ void cvt8(const float4& a, const float4& b,
                                     uint4& hi, uint4& lo) {
    float f[8] = {a.x, a.y, a.z, a.w, b.x, b.y, b.z, b.w};
    unsigned h[4], l[4];
    #pragma unroll
    for (int i = 0; i < 4; i++) {
        float f0 = f[2 * i], f1 = f[2 * i + 1];
        unsigned hp;
        asm("cvt.rn.bf16x2.f32 %0, %1, %2;" : "=r"(hp) : "f"(f1), "f"(f0));
        float h0 = __uint_as_float(hp << 16);
        float h1 = __uint_as_float(hp & 0xFFFF0000u);
        unsigned lp;
        asm("cvt.rn.bf16x2.f32 %0, %1, %2;" : "=r"(lp) : "f"(f1 - h1), "f"(f0 - h0));
        h[i] = hp; l[i] = lp;
    }
    hi = make_uint4(h[0], h[1], h[2], h[3]);
    lo = make_uint4(l[0], l[1], l[2], l[3]);
}

// ---------------- prep: W1^T hi/lo split + global init ----------------
__global__ void prep_kernel(const float* __restrict__ W1) {
    int t = blockIdx.x * 256 + threadIdx.x;          // 16384 threads
    int j = t >> 8, k = t & 255;
    float v = W1[(size_t)k * HID + j];
    __nv_bfloat16 h = __float2bfloat16_rn(v);
    __nv_bfloat16 l = __float2bfloat16_rn(v - __bfloat162float(h));
    g_WtH[j * DIM + k] = h;
    g_WtL[j * DIM + k] = l;
    if (t < NNET) g_count[t] = 0;
    if (t == 0) g_done = 0;
}

// ---------------- score: bf16-split HMMA GEMM, fully double-buffered -------
// w[i] = exp( relu(x[i,:] @ W1 + b1) @ W2 )   (max & b2 cancel in softmax)
__global__ __launch_bounds__(256, 2) void score_kernel(
    const float* __restrict__ x, const float* __restrict__ b1,
    const float* __restrict__ W2, const int* __restrict__ group)
{
    extern __shared__ char dsm[];
    uint32_t raw = smem_u32(dsm);
    uint32_t sb  = (raw + 1023) & ~1023u;
    char* s = dsm + (sb - raw);

    float* sB1  = (float*)(s + OFF_B1);
    float* sW2  = (float*)(s + OFF_W2);
    int*   sCnt = (int*)(s + OFF_CNT);
    int*   sScan= (int*)(s + OFF_SCAN);
    int*   sFlag= (int*)(s + OFF_FLAG);

    const int tid = threadIdx.x;
    const int w   = tid >> 5, l = tid & 31;
    const int row0 = blockIdx.x * TILE_M;
    const float4* __restrict__ x4 = (const float4*)x;

    if (tid < 64) { sB1[tid] = b1[tid]; sW2[tid] = W2[tid]; }
    if (tid < NNET) sCnt[tid] = 0;

    // ldmatrix address precompute
    const uint32_t xw    = (l & 7) * 16;
    const uint32_t a_row = w * 16 + ((l >> 3) & 1) * 8 + (l & 7);
    const uint32_t a_off = a_row * 128;
    const uint32_t a_x   = (a_row & 7) * 16;
    const uint32_t a_cb  = (l >> 4) * 16;
    const uint32_t b_rb  = ((l >> 4) * 8 + (l & 7)) * 128;
    const uint32_t b_cb  = ((l >> 3) & 1) * 16;

    float d[8][4];
    #pragma unroll
    for (int i = 0; i < 8; i++)
        #pragma unroll
        for (int j = 0; j < 4; j++) d[i][j] = 0.f;

    float4 rA[4][2];
    uint4  rBh[2], rBl[2];

    #define LDG_CHUNK(c) do { \
        _Pragma("unroll") for (int it = 0; it < 4; it++) { \
            int f = it * 256 + tid, row = f >> 3, kg = f & 7; \
            const float4* p = x4 + ((size_t)(row0 + row) * 64 + (c) * 16 + kg * 2); \
            rA[it][0] = p[0]; rA[it][1] = p[1]; } \
        _Pragma("unroll") for (int it = 0; it < 2; it++) { \
            int f = it * 256 + tid, n = f >> 3, kg = f & 7; \
            int src = n * DIM + (c) * 64 + kg * 8; \
            rBh[it] = *(const uint4*)(g_WtH + src); \
            rBl[it] = *(const uint4*)(g_WtL + src); } \
    } while (0)

    #define STS_CHUNK(buf) do { \
        uint32_t ab = OFF_A + (buf) * 32768, bb = OFF_B + (buf) * 16384; \
        _Pragma("unroll") for (int it = 0; it < 4; it++) { \
            int f = it * 256 + tid, row = f >> 3, kg = f & 7; \
            uint32_t off = row * 128 + ((kg * 16) ^ ((row & 7) * 16)); \
            uint4 hi, lo; cvt8(rA[it][0], rA[it][1], hi, lo); \
            *(uint4*)(s + ab + off) = hi; \
            *(uint4*)(s + ab + 16384 + off) = lo; } \
        _Pragma("unroll") for (int it = 0; it < 2; it++) { \
            int f = it * 256 + tid, n = f >> 3, kg = f & 7; \
            uint32_t off = n * 128 + ((kg * 16) ^ ((n & 7) * 16)); \
            *(uint4*)(s + bb + off) = rBh[it]; \
            *(uint4*)(s + bb + 8192 + off) = rBl[it]; } \
    } while (0)

    LDG_CHUNK(0);
    STS_CHUNK(0);
    __syncthreads();

    #pragma unroll
    for (int c = 0; c < 4; c++) {
        if (c < 3) LDG_CHUNK(c + 1);          // DRAM latency hides under MMAs

        const uint32_t AHb = sb + OFF_A + (c & 1) * 32768;
        const uint32_t ALb = AHb + 16384;
        const uint32_t BHc = sb + OFF_B + (c & 1) * 16384;
        const uint32_t BLc = BHc + 8192;

        #pragma unroll
        for (int t = 0; t < 4; t++) {
            const uint32_t tcol = t * 32;
            uint32_t ah[4], al[4];
            uint32_t aaddr = a_off + ((tcol + a_cb) ^ a_x);
            LDSM4(ah, AHb + aaddr);
            LDSM4(al, ALb + aaddr);
            #pragma unroll
            for (int q = 0; q < 4; q++) {
                uint32_t bh[4], bl[4];
                uint32_t baddr = q * 2048 + b_rb + ((tcol + b_cb) ^ xw);
                LDSM4(bh, BHc + baddr);
                LDSM4(bl, BLc + baddr);
                MMA(d[2 * q],     ah, bh[0], bh[1]);
                MMA(d[2 * q],     al, bh[0], bh[1]);
                MMA(d[2 * q],     ah, bl[0], bl[1]);
                MMA(d[2 * q + 1], ah, bh[2], bh[3]);
                MMA(d[2 * q + 1], al, bh[2], bh[3]);
                MMA(d[2 * q + 1], ah, bl[2], bl[3]);
            }
        }
        if (c < 3) STS_CHUNK((c + 1) & 1);    // overlapped with other warps' MMAs
        __syncthreads();
    }

    // ---- epilogue: w = exp(relu(D + b1) . W2), quad reduce, write + hist ----
    float sA = 0.f, sB = 0.f;
    #pragma unroll
    for (int nt = 0; nt < 8; nt++) {
        int j0 = nt * 8 + (l & 3) * 2;
        float b0 = sB1[j0], b1v = sB1[j0 + 1];
        float w0 = sW2[j0], w1v = sW2[j0 + 1];
        sA += fmaxf(d[nt][0] + b0, 0.f) * w0 + fmaxf(d[nt][1] + b1v, 0.f) * w1v;
        sB += fmaxf(d[nt][2] + b0, 0.f) * w0 + fmaxf(d[nt][3] + b1v, 0.f) * w1v;
    }
    sA += __shfl_xor_sync(0xffffffffu, sA, 1);
    sA += __shfl_xor_sync(0xffffffffu, sA, 2);
    sB += __shfl_xor_sync(0xffffffffu, sB, 1);
    sB += __shfl_xor_sync(0xffffffffu, sB, 2);

    if ((l & 3) == 0) {
        int r1 = w * 16 + (l >> 2);
        int r2 = r1 + 8;
        g_w[row0 + r1] = __expf(sA);    // scores |s|<~6: exp overflow-safe
        g_w[row0 + r2] = __expf(sB);
        atomicAdd(&sCnt[group[row0 + r1]], 1);
        atomicAdd(&sCnt[group[row0 + r2]], 1);
    }
    __syncthreads();

    if (tid < NNET && sCnt[tid] > 0) atomicAdd(&g_count[tid], sCnt[tid]);
    __threadfence();
    __syncthreads();

    // last block: 128-entry exclusive scan
    if (tid == 0) {
        int t = atomicAdd(&g_done, 1);
        *sFlag = (t == (int)gridDim.x - 1);
    }
    __syncthreads();
    if (*sFlag) {
        if (tid < NNET) sScan[tid] = g_count[tid];
        __syncthreads();
        if (tid < NNET) {
            int acc = 0;
            for (int i = 0; i < tid; i++) acc += sScan[i];
            g_offset[tid] = acc;
            g_cursor[tid] = acc;
        }
        if (tid == 0) g_done = 0;
    }
}

// ---------------- scatter into per-group bins (block-aggregated) -----------
__global__ __launch_bounds__(1024) void scatter_kernel(const int* __restrict__ group) {
    __shared__ int sCnt[NNET];
    __shared__ int sCur[NNET];
    int tid = threadIdx.x;
    int i = blockIdx.x * 1024 + tid;
    if (tid < NNET) sCnt[tid] = 0;
    __syncthreads();
    int g = group[i];
    float w = g_w[i];
    atomicAdd(&sCnt[g], 1);
    __syncthreads();
    if (tid < NNET && sCnt[tid] > 0)
        sCur[tid] = atomicAdd(&g_cursor[tid], sCnt[tid]);
    __syncthreads();
    int pos = atomicAdd(&sCur[g], 1);
    g_pair[pos] = ((ull)(unsigned)__float_as_int(w) << 32) | (unsigned)i;
}

// ---------------- weighted pooling (denom computed in-flight) --------------
__global__ __launch_bounds__(256) void pool_kernel(
    const float* __restrict__ x, float* __restrict__ out)
{
    int g     = blockIdx.x >> 3;
    int chunk = blockIdx.x & 7;
    int rs    = threadIdx.x >> 3;
    int ct    = threadIdx.x & 7;
    int start = g_offset[g];
    int cnt   = g_count[g];
    int cb    = chunk * 8 + ct;
    const float4* __restrict__ x4 = (const float4*)x;

    float4 acc = make_float4(0.f, 0.f, 0.f, 0.f);
    float wsum = 0.f;
    int r = rs;
    for (; r + 96 < cnt; r += 128) {
        ull p0 = g_pair[start + r];
        ull p1 = g_pair[start + r + 32];
        ull p2 = g_pair[start + r + 64];
        ull p3 = g_pair[start + r + 96];
        float w0 = __int_as_float((int)(p0 >> 32));
        float w1 = __int_as_float((int)(p1 >> 32));
        float w2 = __int_as_float((int)(p2 >> 32));
        float w3 = __int_as_float((int)(p3 >> 32));
        if (ct == 0) wsum += (w0 + w1) + (w2 + w3);
        float4 v0 = x4[(size_t)(unsigned)p0 * 64 + cb];
        float4 v1 = x4[(size_t)(unsigned)p1 * 64 + cb];
        float4 v2 = x4[(size_t)(unsigned)p2 * 64 + cb];
        float4 v3 = x4[(size_t)(unsigned)p3 * 64 + cb];
        acc.x += w0 * v0.x; acc.y += w0 * v0.y; acc.z += w0 * v0.z; acc.w += w0 * v0.w;
        acc.x += w1 * v1.x; acc.y += w1 * v1.y; acc.z += w1 * v1.z; acc.w += w1 * v1.w;
        acc.x += w2 * v2.x; acc.y += w2 * v2.y; acc.z += w2 * v2.z; acc.w += w2 * v2.w;
        acc.x += w3 * v3.x; acc.y += w3 * v3.y; acc.z += w3 * v3.z; acc.w += w3 * v3.w;
    }
    for (; r < cnt; r += 32) {
        ull p = g_pair[start + r];
        float w = __int_as_float((int)(p >> 32));
        if (ct == 0) wsum += w;
        float4 v = x4[(size_t)(unsigned)p * 64 + cb];
        acc.x += w * v.x; acc.y += w * v.y; acc.z += w * v.z; acc.w += w * v.w;
    }

    __shared__ float4 red[32][8];
    __shared__ float  wred[32];
    red[rs][ct] = acc;
    if (ct == 0) wred[rs] = wsum;
    __syncthreads();
    #pragma unroll
    for (int o = 16; o >= 1; o >>= 1) {
        if (rs < o) {
            float4 t = red[rs + o][ct];
            float4 u = red[rs][ct];
            u.x += t.x; u.y += t.y; u.z += t.z; u.w += t.w;
            red[rs][ct] = u;
            if (ct == 0) wred[rs] += wred[rs + o];
        }
        __syncthreads();
    }
    if (rs == 0) {
        float den = wred[0];
        float inv = (den > 0.f) ? (1.f / den) : 0.f;
        float4 v = red[0][ct];
        v.x *= inv; v.y *= inv; v.z *= inv; v.w *= inv;
        ((float4*)out)[(size_t)g * 64 + cb] = v;
    }
}

// ---------------- launch ----------------
extern "C" void kernel_launch(void* const* d_in, const int* in_sizes, int n_in,
                              void* d_out, int out_size) {
    const float* x   = (const float*)d_in[0];
    const int*   grp = (const int*)d_in[1];
    const float* W1  = (const float*)d_in[2];
    const float* b1  = (const float*)d_in[3];
    const float* W2  = (const float*)d_in[4];
    // b2 (d_in[5]) cancels under softmax shift-invariance.

    cudaFuncSetAttribute(score_kernel,
        cudaFuncAttributeMaxDynamicSharedMemorySize, DSMEM_BYTES);

    prep_kernel<<<64, 256>>>(W1);
    score_kernel<<<NTILE, 256, DSMEM_BYTES>>>(x, b1, W2, grp);
    scatter_kernel<<<N_ROI / 1024, 1024>>>(grp);
    pool_kernel<<<NNET * 8, 256>>>(x, (float*)d_out);
}